// round 3
// baseline (speedup 1.0000x reference)
#include <cuda_runtime.h>

#define BB 128          // graphs
#define NN 68           // landmarks per graph
#define CC 3            // input channels
#define PP 32           // patch
#define KK 16           // conv kernels
#define FD 64           // feature dim
#define GH 128          // gcn hidden
#define OUTD 2
#define EG (8*NN)       // 544 edges per graph
#define TT (BB*NN)      // 8704 nodes
#define FLAT (KK*(PP/2)*(PP/2))   // 4096

typedef unsigned long long u64;

// ---- scratch (allocation-free: device globals) ----
__device__ float g_flat[(size_t)TT * FLAT];   // ~142.6 MB
__device__ float g_feats[TT * FD];
__device__ float g_xw[TT * GH];

// ---- packed f32x2 helpers (Blackwell packed fp32 pipe) ----
__device__ __forceinline__ u64 pk2(float lo, float hi) {
    u64 r; asm("mov.b64 %0, {%1, %2};" : "=l"(r) : "f"(lo), "f"(hi)); return r;
}
__device__ __forceinline__ void upk2(u64 v, float& lo, float& hi) {
    asm("mov.b64 {%0, %1}, %2;" : "=f"(lo), "=f"(hi) : "l"(v));
}
__device__ __forceinline__ u64 fma2(u64 a, u64 b, u64 c) {
    u64 d; asm("fma.rn.f32x2 %0, %1, %2, %3;" : "=l"(d) : "l"(a), "l"(b), "l"(c)); return d;
}

// ============================================================
// Stage 1: per-landmark conv3x3 (SAME) + bias + relu + maxpool2x2
// thread = pooled pixel; overlapping packed window pairs in regs,
// weights duplicated as float2 in smem -> 54 FFMA2 per k
// ============================================================
__global__ __launch_bounds__(256) void conv_pool_kernel(
    const float* __restrict__ x,
    const float* __restrict__ conv_w,
    const float* __restrict__ conv_b)
{
    int t = blockIdx.x;
    int n = t % NN;
    __shared__ float  xs[CC][PP][PP];     // 12 KB
    __shared__ float2 wp[KK * 27];        // duplicated weights, 3456 B
    __shared__ float  bsh[KK];

    int tid = threadIdx.x;
    const float4* xp4 = (const float4*)(x + (size_t)t * (CC * PP * PP));
    #pragma unroll
    for (int i = 0; i < 3; i++)
        ((float4*)xs)[tid + i * 256] = xp4[tid + i * 256];
    for (int i = tid; i < KK * 27; i += 256) {
        float w = conv_w[(size_t)n * KK * 27 + i];
        wp[i] = make_float2(w, w);
    }
    if (tid < KK) bsh[tid] = conv_b[n * KK + tid];
    __syncthreads();

    int pi = tid >> 4, pj = tid & 15;
    int y0 = 2 * pi, x0 = 2 * pj;

    // overlapping pairs: pr[c][dy][j] = (win[dy][j], win[dy][j+1]), zero padded
    u64 pr[CC][4][3];
    #pragma unroll
    for (int c = 0; c < CC; c++) {
        #pragma unroll
        for (int dy = 0; dy < 4; dy++) {
            int yy = y0 + dy - 1;
            float w0, w1, w2, w3;
            if (yy >= 0 && yy < PP) {
                w0 = (x0 - 1 >= 0) ? xs[c][yy][x0 - 1] : 0.f;
                w1 = xs[c][yy][x0];
                w2 = xs[c][yy][x0 + 1];
                w3 = (x0 + 2 < PP) ? xs[c][yy][x0 + 2] : 0.f;
            } else { w0 = w1 = w2 = w3 = 0.f; }
            pr[c][dy][0] = pk2(w0, w1);
            pr[c][dy][1] = pk2(w1, w2);
            pr[c][dy][2] = pk2(w2, w3);
        }
    }

    float* outp = &g_flat[(size_t)t * FLAT + tid];
    const u64* wpp = (const u64*)wp;
    #pragma unroll 1
    for (int k = 0; k < KK; k++) {
        float b = bsh[k];
        u64 A0 = pk2(b, b);     // (a00, a01)
        u64 A1 = A0;            // (a10, a11)
        const u64* w = wpp + k * 27;
        #pragma unroll
        for (int c = 0; c < CC; c++)
            #pragma unroll
            for (int ky = 0; ky < 3; ky++)
                #pragma unroll
                for (int kx = 0; kx < 3; kx++) {
                    u64 wv = w[c * 9 + ky * 3 + kx];
                    A0 = fma2(pr[c][ky    ][kx], wv, A0);
                    A1 = fma2(pr[c][ky + 1][kx], wv, A1);
                }
        float a00, a01, a10, a11;
        upk2(A0, a00, a01);
        upk2(A1, a10, a11);
        float m = fmaxf(fmaxf(a00, a01), fmaxf(a10, a11));
        outp[k * 256] = fmaxf(m, 0.f);   // relu(max) == max(relu)
    }
}

// ============================================================
// Stage 2: per-landmark linear 4096 -> 64, relu  (packed f32x2)
// block = (landmark n, 64-graph slab); thread = 2 outputs x 8 graphs
// fshT transposed in smem so graph pairs are contiguous
// ============================================================
__global__ __launch_bounds__(256) void lin1_kernel(
    const float* __restrict__ lin1_w,
    const float* __restrict__ lin1_b)
{
    int n  = blockIdx.x;
    int b0 = blockIdx.y * 64;
    __shared__ float wsh[64 * 64];       // [ff][o]           16 KB
    __shared__ float fshT[64 * 68];      // [ff][graph], pad68 17 KB

    int tid = threadIdx.x;
    int o2  = tid & 31;                  // output pair id: o = 2*o2, 2*o2+1
    int gq  = tid >> 5;                  // graph octet 0..7

    u64 acc[2][4];
    #pragma unroll
    for (int a = 0; a < 2; a++)
        #pragma unroll
        for (int b = 0; b < 4; b++) acc[a][b] = 0ull;

    const float* wbase = lin1_w + (size_t)n * FLAT * FD;

    for (int f0 = 0; f0 < FLAT; f0 += 64) {
        __syncthreads();
        const float* wsrc = wbase + (size_t)f0 * FD;
        #pragma unroll
        for (int j = 0; j < 16; j++)
            wsh[tid + j * 256] = wsrc[tid + j * 256];
        #pragma unroll
        for (int j = 0; j < 16; j++) {
            int idx = tid + j * 256;
            int ff = idx & 63, bi = idx >> 6;
            fshT[ff * 68 + bi] = g_flat[(size_t)((b0 + bi) * NN + n) * FLAT + f0 + ff];
        }
        __syncthreads();

        #pragma unroll 8
        for (int ff = 0; ff < 64; ff++) {
            float wlo = wsh[ff * 64 + 2 * o2];
            float whi = wsh[ff * 64 + 2 * o2 + 1];
            u64 W0 = pk2(wlo, wlo);
            u64 W1 = pk2(whi, whi);
            const ulonglong2* fp = (const ulonglong2*)&fshT[ff * 68 + gq * 8];
            ulonglong2 fA = fp[0];       // graphs (0,1),(2,3)
            ulonglong2 fB = fp[1];       // graphs (4,5),(6,7)
            acc[0][0] = fma2(fA.x, W0, acc[0][0]);
            acc[1][0] = fma2(fA.x, W1, acc[1][0]);
            acc[0][1] = fma2(fA.y, W0, acc[0][1]);
            acc[1][1] = fma2(fA.y, W1, acc[1][1]);
            acc[0][2] = fma2(fB.x, W0, acc[0][2]);
            acc[1][2] = fma2(fB.x, W1, acc[1][2]);
            acc[0][3] = fma2(fB.y, W0, acc[0][3]);
            acc[1][3] = fma2(fB.y, W1, acc[1][3]);
        }
    }

    #pragma unroll
    for (int op = 0; op < 2; op++) {
        int o = 2 * o2 + op;
        float bias = lin1_b[n * FD + o];
        #pragma unroll
        for (int gp = 0; gp < 4; gp++) {
            float vlo, vhi;
            upk2(acc[op][gp], vlo, vhi);
            int ga = b0 + gq * 8 + 2 * gp;
            g_feats[(size_t)(ga * NN + n) * FD + o]       = fmaxf(vlo + bias, 0.f);
            g_feats[(size_t)((ga + 1) * NN + n) * FD + o] = fmaxf(vhi + bias, 0.f);
        }
    }
}

// ============================================================
// Stage 3: xw = feats @ gcn_w   (4 nodes / block, gcn_w in smem)
// ============================================================
__global__ __launch_bounds__(512) void gcn_xw_kernel(const float* __restrict__ gcn_w)
{
    int t0 = blockIdx.x * 4;
    __shared__ float wsm[FD * GH];       // 32 KB
    __shared__ float fsm[4 * FD];
    int tid = threadIdx.x;
    #pragma unroll
    for (int i = 0; i < 16; i++)
        wsm[tid + i * 512] = gcn_w[tid + i * 512];
    if (tid < 4 * FD) fsm[tid] = g_feats[t0 * FD + tid];
    __syncthreads();

    int j = tid & 127, nd = tid >> 7;
    float acc = 0.f;
    #pragma unroll
    for (int c = 0; c < FD; c++)
        acc = fmaf(fsm[nd * FD + c], wsm[c * GH + j], acc);
    g_xw[(t0 + nd) * GH + j] = acc;
}

// ============================================================
// Stage 4 (fused): degrees + deterministic CSR + GCN aggregate
//                  + mean-pool + MLP head. One block per graph.
// ============================================================
__global__ __launch_bounds__(256) void gcn_head_kernel(
    const int* __restrict__ edge_index,
    const float* __restrict__ gcn_b,
    const float* __restrict__ w1, const float* __restrict__ b1,
    const float* __restrict__ w2, const float* __restrict__ b2,
    float* __restrict__ out)
{
    int g = blockIdx.x;
    __shared__ int   s_dst[EG];
    __shared__ int   s_src[EG];
    __shared__ int   adj_src[EG];
    __shared__ float adj_norm[EG];
    __shared__ int   cnt[NN];
    __shared__ int   start[NN + 1];
    __shared__ float dis[NN];
    __shared__ float bsm[GH];
    __shared__ float sh_h[NN][GH];       // 34.8 KB
    __shared__ float gsm[GH];
    __shared__ float zsm[GH / 2];

    int tid = threadIdx.x;
    const int* srcA = edge_index + g * EG;
    const int* dstA = edge_index + BB * EG + g * EG;

    if (tid < NN) cnt[tid] = 1;          // self loop
    if (tid < GH) bsm[tid] = gcn_b[tid];
    __syncthreads();

    for (int e = tid; e < EG; e += 256) {
        int s = srcA[e] - g * NN;
        int d = dstA[e] - g * NN;
        s_src[e] = s;
        s_dst[e] = d;
        atomicAdd(&cnt[d], 1);
    }
    __syncthreads();

    if (tid < NN) dis[tid] = rsqrtf((float)cnt[tid]);
    if (tid == 0) {
        int s = 0;
        for (int i = 0; i < NN; i++) { start[i] = s; s += cnt[i] - 1; }
        start[NN] = s;
    }
    __syncthreads();

    // deterministic placement: edge e -> slot start[d] + (#earlier edges, same d)
    for (int e = tid; e < EG; e += 256) {
        int d = s_dst[e];
        int r = 0;
        for (int e2 = 0; e2 < e; e2++) r += (s_dst[e2] == d);
        int p = start[d] + r;
        adj_src[p]  = s_src[e];
        adj_norm[p] = dis[s_src[e]] * dis[d];
    }
    __syncthreads();

    // gather: 68 nodes x 128 channels
    int ch = tid & 127, half = tid >> 7;
    const float* xwg = g_xw + (size_t)g * NN * GH;
    for (int n0 = half; n0 < NN; n0 += 2) {
        float dn = dis[n0];
        float acc = dn * dn * xwg[n0 * GH + ch];   // self loop
        int p1 = start[n0 + 1];
        for (int p = start[n0]; p < p1; p++)
            acc = fmaf(adj_norm[p], xwg[adj_src[p] * GH + ch], acc);
        sh_h[n0][ch] = fmaxf(acc + bsm[ch], 0.f);
    }
    __syncthreads();

    // mean pool
    if (tid < GH) {
        float s = 0.f;
        #pragma unroll 4
        for (int i = 0; i < NN; i++) s += sh_h[i][tid];
        gsm[tid] = s * (1.0f / (float)NN);
    }
    __syncthreads();

    if (tid < GH / 2) {
        float acc = b1[tid];
        #pragma unroll
        for (int c = 0; c < GH; c++)
            acc = fmaf(gsm[c], w1[c * (GH / 2) + tid], acc);
        zsm[tid] = fmaxf(acc, 0.f);
    }
    __syncthreads();

    if (tid < OUTD) {
        float acc = b2[tid];
        for (int j = 0; j < GH / 2; j++)
            acc = fmaf(zsm[j], w2[j * OUTD + tid], acc);
        out[g * OUTD + tid] = acc;
    }
}

extern "C" void kernel_launch(void* const* d_in, const int* in_sizes, int n_in,
                              void* d_out, int out_size)
{
    const float* x        = (const float*)d_in[0];
    const int*   edge_idx = (const int*)  d_in[1];
    const float* conv_w   = (const float*)d_in[3];
    const float* conv_b   = (const float*)d_in[4];
    const float* lin1_w   = (const float*)d_in[5];
    const float* lin1_b   = (const float*)d_in[6];
    const float* gcn_w    = (const float*)d_in[7];
    const float* gcn_b    = (const float*)d_in[8];
    const float* mlp_w1   = (const float*)d_in[9];
    const float* mlp_b1   = (const float*)d_in[10];
    const float* mlp_w2   = (const float*)d_in[11];
    const float* mlp_b2   = (const float*)d_in[12];
    float* out = (float*)d_out;

    conv_pool_kernel<<<TT, 256>>>(x, conv_w, conv_b);
    lin1_kernel<<<dim3(NN, 2), 256>>>(lin1_w, lin1_b);
    gcn_xw_kernel<<<TT / 4, 512>>>(gcn_w);
    gcn_head_kernel<<<BB, 256>>>(edge_idx, gcn_b, mlp_w1, mlp_b1, mlp_w2, mlp_b2, out);
}

// round 4
// speedup vs baseline: 1.1808x; 1.1808x over previous
#include <cuda_runtime.h>

#define BB 128          // graphs
#define NN 68           // landmarks per graph
#define CC 3            // input channels
#define PP 32           // patch
#define KK 16           // conv kernels
#define FD 64           // feature dim
#define GH 128          // gcn hidden
#define OUTD 2
#define EG (8*NN)       // 544 edges per graph
#define TT (BB*NN)      // 8704 nodes
#define FLAT (KK*(PP/2)*(PP/2))   // 4096

// ---- scratch (allocation-free: device globals) ----
__device__ float g_flat[(size_t)TT * FLAT];   // ~142.6 MB
__device__ float g_feats[TT * FD];

// ============================================================
// Stage 1: Winograd F(2x2,3x3) conv + bias + relu + maxpool2x2
// thread = pooled pixel = one Winograd tile. Input transform done
// once per thread (V, 48 regs), reused across all 16 kernels.
// Per k: 16 MUL + 32 FMA + 24 ADD on fma pipe (vs 108 direct).
// ============================================================
__global__ __launch_bounds__(256) void conv_pool_kernel(
    const float* __restrict__ x,
    const float* __restrict__ conv_w,
    const float* __restrict__ conv_b)
{
    int t = blockIdx.x;
    int n = t % NN;
    __shared__ float xs[CC][PP][PP];        // 12 KB
    __shared__ float usm[KK][CC][16];       // transformed weights, 3 KB
    __shared__ float bsh[KK];

    int tid = threadIdx.x;
    const float4* xp4 = (const float4*)(x + (size_t)t * (CC * PP * PP));
    #pragma unroll
    for (int i = 0; i < 3; i++)
        ((float4*)xs)[tid + i * 256] = xp4[tid + i * 256];

    // weight transform U = G g G^T  (48 (k,c) pairs, one thread each)
    if (tid < KK * CC) {
        int k = tid / CC, c = tid % CC;
        const float* gw = conv_w + ((size_t)n * KK + k) * 27 + c * 9;
        float g0 = gw[0], g1 = gw[1], g2 = gw[2];
        float g3 = gw[3], g4 = gw[4], g5 = gw[5];
        float g6 = gw[6], g7 = gw[7], g8 = gw[8];
        // T = G * g   (4x3):  rows r0,(r0+r1+r2)/2,(r0-r1+r2)/2,r2
        float T[4][3];
        T[0][0] = g0;                    T[0][1] = g1;                    T[0][2] = g2;
        T[1][0] = 0.5f*(g0+g3+g6);       T[1][1] = 0.5f*(g1+g4+g7);       T[1][2] = 0.5f*(g2+g5+g8);
        T[2][0] = 0.5f*(g0-g3+g6);       T[2][1] = 0.5f*(g1-g4+g7);       T[2][2] = 0.5f*(g2-g5+g8);
        T[3][0] = g6;                    T[3][1] = g7;                    T[3][2] = g8;
        #pragma unroll
        for (int i = 0; i < 4; i++) {
            float t0 = T[i][0], t1 = T[i][1], t2 = T[i][2];
            usm[k][c][i*4+0] = t0;
            usm[k][c][i*4+1] = 0.5f*(t0+t1+t2);
            usm[k][c][i*4+2] = 0.5f*(t0-t1+t2);
            usm[k][c][i*4+3] = t2;
        }
    }
    if (tid < KK) bsh[tid] = conv_b[n * KK + tid];
    __syncthreads();

    int pi = tid >> 4, pj = tid & 15;
    int y0 = 2 * pi, x0 = 2 * pj;

    // V = B^T d B per channel (zero-padded 4x4 window)
    float V[CC][16];
    #pragma unroll
    for (int c = 0; c < CC; c++) {
        float d[4][4];
        #pragma unroll
        for (int dy = 0; dy < 4; dy++) {
            int yy = y0 + dy - 1;
            #pragma unroll
            for (int dx = 0; dx < 4; dx++) {
                int xx = x0 + dx - 1;
                d[dy][dx] = (yy >= 0 && yy < PP && xx >= 0 && xx < PP)
                            ? xs[c][yy][xx] : 0.f;
            }
        }
        float tt[4][4];
        #pragma unroll
        for (int j = 0; j < 4; j++) {
            tt[0][j] = d[0][j] - d[2][j];
            tt[1][j] = d[1][j] + d[2][j];
            tt[2][j] = d[2][j] - d[1][j];
            tt[3][j] = d[1][j] - d[3][j];
        }
        #pragma unroll
        for (int i = 0; i < 4; i++) {
            V[c][i*4+0] = tt[i][0] - tt[i][2];
            V[c][i*4+1] = tt[i][1] + tt[i][2];
            V[c][i*4+2] = tt[i][2] - tt[i][1];
            V[c][i*4+3] = tt[i][1] - tt[i][3];
        }
    }

    float* outp = &g_flat[(size_t)t * FLAT + tid];
    #pragma unroll 1
    for (int k = 0; k < KK; k++) {
        float M[16];
        #pragma unroll
        for (int c = 0; c < CC; c++) {
            const float4* up = (const float4*)usm[k][c];
            #pragma unroll
            for (int q = 0; q < 4; q++) {
                float4 u = up[q];
                if (c == 0) {
                    M[q*4+0] = V[0][q*4+0] * u.x;
                    M[q*4+1] = V[0][q*4+1] * u.y;
                    M[q*4+2] = V[0][q*4+2] * u.z;
                    M[q*4+3] = V[0][q*4+3] * u.w;
                } else {
                    M[q*4+0] = fmaf(V[c][q*4+0], u.x, M[q*4+0]);
                    M[q*4+1] = fmaf(V[c][q*4+1], u.y, M[q*4+1]);
                    M[q*4+2] = fmaf(V[c][q*4+2], u.z, M[q*4+2]);
                    M[q*4+3] = fmaf(V[c][q*4+3], u.w, M[q*4+3]);
                }
            }
        }
        // Y = A^T M A
        float p0[4], p1[4];
        #pragma unroll
        for (int j = 0; j < 4; j++) {
            p0[j] = M[0*4+j] + M[1*4+j] + M[2*4+j];
            p1[j] = M[1*4+j] - M[2*4+j] - M[3*4+j];
        }
        float y00 = p0[0] + p0[1] + p0[2];
        float y01 = p0[1] - p0[2] - p0[3];
        float y10 = p1[0] + p1[1] + p1[2];
        float y11 = p1[1] - p1[2] - p1[3];
        float m = fmaxf(fmaxf(y00, y01), fmaxf(y10, y11));
        outp[k * 256] = fmaxf(m + bsh[k], 0.f);   // relu(max+b)==max(relu(.+b))
    }
}

// ============================================================
// Stage 2: per-landmark linear 4096 -> 64, relu (R2 version)
// ============================================================
__global__ __launch_bounds__(256) void lin1_kernel(
    const float* __restrict__ lin1_w,
    const float* __restrict__ lin1_b)
{
    int n  = blockIdx.x;
    int b0 = blockIdx.y * 32;
    __shared__ float  wsh[64 * 64];      // [ff][o]   16 KB
    __shared__ float4 fsh4[32 * 16];     // [bi][ff/4] 8 KB
    float* fsh = (float*)fsh4;

    int tid  = threadIdx.x;
    int o    = tid & 63;
    int brow = tid >> 6;                 // 0..3

    float acc[8];
    #pragma unroll
    for (int i = 0; i < 8; i++) acc[i] = 0.f;

    const float* wbase = lin1_w + (size_t)n * FLAT * FD;

    for (int f0 = 0; f0 < FLAT; f0 += 64) {
        __syncthreads();
        const float* wsrc = wbase + (size_t)f0 * FD;
        #pragma unroll
        for (int j = 0; j < 16; j++)
            wsh[tid + j * 256] = wsrc[tid + j * 256];
        #pragma unroll
        for (int j = 0; j < 8; j++) {
            int idx = tid + j * 256;
            int bi = idx >> 6, ff = idx & 63;
            fsh[idx] = g_flat[(size_t)((b0 + bi) * NN + n) * FLAT + f0 + ff];
        }
        __syncthreads();
        #pragma unroll 4
        for (int gquad = 0; gquad < 16; gquad++) {
            float w0 = wsh[(4 * gquad + 0) * 64 + o];
            float w1 = wsh[(4 * gquad + 1) * 64 + o];
            float w2 = wsh[(4 * gquad + 2) * 64 + o];
            float w3 = wsh[(4 * gquad + 3) * 64 + o];
            #pragma unroll
            for (int i = 0; i < 8; i++) {
                float4 fv = fsh4[(brow * 8 + i) * 16 + gquad];
                acc[i] = fmaf(fv.x, w0, acc[i]);
                acc[i] = fmaf(fv.y, w1, acc[i]);
                acc[i] = fmaf(fv.z, w2, acc[i]);
                acc[i] = fmaf(fv.w, w3, acc[i]);
            }
        }
    }

    float bias = lin1_b[n * FD + o];
    #pragma unroll
    for (int i = 0; i < 8; i++) {
        int b = b0 + brow * 8 + i;
        g_feats[(size_t)(b * NN + n) * FD + o] = fmaxf(acc[i] + bias, 0.f);
    }
}

// ============================================================
// Stage 3 (fused): xw GEMM + degrees + deterministic CSR +
// GCN aggregate + mean-pool + MLP head. One block per graph.
// No atomics, no float-order nondeterminism. ~113 KB dyn smem.
// ============================================================
struct GcnSmem {
    float wsm[FD * GH];                  // 32768 B
    float xw[NN * GH];                   // 34816 B
    union { float feats[NN * FD]; float h[NN * GH]; } u;  // 34816 B
    int   s_src[EG];
    int   s_dst[EG];
    int   adj_src[EG];
    float adj_norm[EG];
    int   cnt[NN];
    int   startn[NN + 1];
    float dis[NN];
    float bsm[GH];
    float gsm[GH];
    float zsm[GH / 2];
};

__global__ __launch_bounds__(256) void gcn_head_kernel(
    const int* __restrict__ edge_index,
    const float* __restrict__ gcn_w,
    const float* __restrict__ gcn_b,
    const float* __restrict__ w1, const float* __restrict__ b1,
    const float* __restrict__ w2, const float* __restrict__ b2,
    float* __restrict__ out)
{
    extern __shared__ char smem_raw[];
    GcnSmem* S = (GcnSmem*)smem_raw;
    int g = blockIdx.x;
    int tid = threadIdx.x;
    const int* srcA = edge_index + g * EG;
    const int* dstA = edge_index + BB * EG + g * EG;

    #pragma unroll
    for (int i = 0; i < FD * GH / 256; i++)
        S->wsm[tid + i * 256] = gcn_w[tid + i * 256];
    for (int i = tid; i < NN * FD; i += 256)
        S->u.feats[i] = g_feats[(size_t)g * NN * FD + i];
    for (int e = tid; e < EG; e += 256) {
        S->s_src[e] = srcA[e] - g * NN;
        S->s_dst[e] = dstA[e] - g * NN;
    }
    if (tid < GH) S->bsm[tid] = gcn_b[tid];
    __syncthreads();

    // xw = feats @ gcn_w (per node row)
    int ch = tid & 127, half = tid >> 7;
    for (int nd = half; nd < NN; nd += 2) {
        const float* fr = &S->u.feats[nd * FD];
        float acc = 0.f;
        #pragma unroll
        for (int c = 0; c < FD; c++)
            acc = fmaf(fr[c], S->wsm[c * GH + ch], acc);
        S->xw[nd * GH + ch] = acc;
    }

    // degree count (thread-per-node scan, deterministic, no atomics)
    if (tid < NN) {
        int c = 0;
        for (int e = 0; e < EG; e++) c += (S->s_dst[e] == tid);
        S->cnt[tid] = c;
        S->dis[tid] = rsqrtf((float)(c + 1));   // + self loop
    }
    __syncthreads();

    if (tid == 0) {
        int s = 0;
        for (int i = 0; i < NN; i++) { S->startn[i] = s; s += S->cnt[i]; }
        S->startn[NN] = s;
    }
    __syncthreads();

    // CSR placement in original edge order (deterministic)
    if (tid < NN) {
        int p = S->startn[tid];
        float dn = S->dis[tid];
        for (int e = 0; e < EG; e++) {
            if (S->s_dst[e] == tid) {
                int sN = S->s_src[e];
                S->adj_src[p]  = sN;
                S->adj_norm[p] = S->dis[sN] * dn;
                p++;
            }
        }
    }
    __syncthreads();

    // aggregate -> h (h aliases feats; feats dead after xw + syncs above)
    for (int nd = half; nd < NN; nd += 2) {
        float dn = S->dis[nd];
        float acc = dn * dn * S->xw[nd * GH + ch];     // self loop
        int p1 = S->startn[nd + 1];
        for (int p = S->startn[nd]; p < p1; p++)
            acc = fmaf(S->adj_norm[p], S->xw[S->adj_src[p] * GH + ch], acc);
        S->u.h[nd * GH + ch] = fmaxf(acc + S->bsm[ch], 0.f);
    }
    __syncthreads();

    // mean pool over 68 nodes
    if (tid < GH) {
        float s = 0.f;
        #pragma unroll 4
        for (int i = 0; i < NN; i++) s += S->u.h[i * GH + tid];
        S->gsm[tid] = s * (1.0f / (float)NN);
    }
    __syncthreads();

    if (tid < GH / 2) {
        float acc = b1[tid];
        #pragma unroll
        for (int c = 0; c < GH; c++)
            acc = fmaf(S->gsm[c], w1[c * (GH / 2) + tid], acc);
        S->zsm[tid] = fmaxf(acc, 0.f);
    }
    __syncthreads();

    if (tid < OUTD) {
        float acc = b2[tid];
        for (int j = 0; j < GH / 2; j++)
            acc = fmaf(S->zsm[j], w2[j * OUTD + tid], acc);
        out[g * OUTD + tid] = acc;
    }
}

extern "C" void kernel_launch(void* const* d_in, const int* in_sizes, int n_in,
                              void* d_out, int out_size)
{
    const float* x        = (const float*)d_in[0];
    const int*   edge_idx = (const int*)  d_in[1];
    const float* conv_w   = (const float*)d_in[3];
    const float* conv_b   = (const float*)d_in[4];
    const float* lin1_w   = (const float*)d_in[5];
    const float* lin1_b   = (const float*)d_in[6];
    const float* gcn_w    = (const float*)d_in[7];
    const float* gcn_b    = (const float*)d_in[8];
    const float* mlp_w1   = (const float*)d_in[9];
    const float* mlp_b1   = (const float*)d_in[10];
    const float* mlp_w2   = (const float*)d_in[11];
    const float* mlp_b2   = (const float*)d_in[12];
    float* out = (float*)d_out;

    cudaFuncSetAttribute(gcn_head_kernel,
                         cudaFuncAttributeMaxDynamicSharedMemorySize,
                         (int)sizeof(GcnSmem));

    conv_pool_kernel<<<TT, 256>>>(x, conv_w, conv_b);
    lin1_kernel<<<dim3(NN, 4), 256>>>(lin1_w, lin1_b);
    gcn_head_kernel<<<BB, 256, sizeof(GcnSmem)>>>(
        edge_idx, gcn_w, gcn_b, mlp_w1, mlp_b1, mlp_w2, mlp_b2, out);
}

// round 5
// speedup vs baseline: 1.2782x; 1.0824x over previous
#include <cuda_runtime.h>
#include <cuda_bf16.h>
#include <cstdint>

#define BB 128          // graphs
#define NN 68           // landmarks per graph
#define CC 3            // input channels
#define PP 32           // patch
#define KK 16           // conv kernels
#define FD 64           // feature dim
#define GH 128          // gcn hidden
#define OUTD 2
#define EG (8*NN)       // 544 edges per graph
#define TT (BB*NN)      // 8704 nodes
#define FLAT (KK*(PP/2)*(PP/2))   // 4096

// ---- scratch (allocation-free: device globals) ----
__device__ __nv_bfloat16 g_fhi[(size_t)TT * FLAT];   // 71.3 MB activation hi
__device__ __nv_bfloat16 g_flo[(size_t)TT * FLAT];   // 71.3 MB activation lo
__device__ __nv_bfloat16 g_whi[(size_t)NN * FLAT * FD];  // 35.7 MB weight hi
__device__ __nv_bfloat16 g_wlo[(size_t)NN * FLAT * FD];  // 35.7 MB weight lo
__device__ float g_part[2][(size_t)BB * NN * FD];        // k-half partial sums

// ============================================================
// Stage 0: split lin1_w into bf16 hi/lo planes (one-shot per call)
// ============================================================
__global__ __launch_bounds__(256) void wsplit_kernel(const float* __restrict__ lin1_w)
{
    size_t i = (size_t)blockIdx.x * 2048 + threadIdx.x;
    #pragma unroll
    for (int j = 0; j < 8; j++, i += 256) {
        float w = lin1_w[i];
        __nv_bfloat16 h = __float2bfloat16(w);
        g_whi[i] = h;
        g_wlo[i] = __float2bfloat16(w - __bfloat162float(h));
    }
}

// ============================================================
// Stage 1: Winograd F(2x2,3x3) conv + bias + relu + maxpool2x2
// outputs split into bf16 hi/lo planes
// ============================================================
__global__ __launch_bounds__(256) void conv_pool_kernel(
    const float* __restrict__ x,
    const float* __restrict__ conv_w,
    const float* __restrict__ conv_b)
{
    int t = blockIdx.x;
    int n = t % NN;
    __shared__ float xs[CC][PP][PP];        // 12 KB
    __shared__ float usm[KK][CC][16];       // transformed weights
    __shared__ float bsh[KK];

    int tid = threadIdx.x;
    const float4* xp4 = (const float4*)(x + (size_t)t * (CC * PP * PP));
    #pragma unroll
    for (int i = 0; i < 3; i++)
        ((float4*)xs)[tid + i * 256] = xp4[tid + i * 256];

    if (tid < KK * CC) {
        int k = tid / CC, c = tid % CC;
        const float* gw = conv_w + ((size_t)n * KK + k) * 27 + c * 9;
        float g0 = gw[0], g1 = gw[1], g2 = gw[2];
        float g3 = gw[3], g4 = gw[4], g5 = gw[5];
        float g6 = gw[6], g7 = gw[7], g8 = gw[8];
        float T[4][3];
        T[0][0] = g0;              T[0][1] = g1;              T[0][2] = g2;
        T[1][0] = 0.5f*(g0+g3+g6); T[1][1] = 0.5f*(g1+g4+g7); T[1][2] = 0.5f*(g2+g5+g8);
        T[2][0] = 0.5f*(g0-g3+g6); T[2][1] = 0.5f*(g1-g4+g7); T[2][2] = 0.5f*(g2-g5+g8);
        T[3][0] = g6;              T[3][1] = g7;              T[3][2] = g8;
        #pragma unroll
        for (int i = 0; i < 4; i++) {
            float t0 = T[i][0], t1 = T[i][1], t2 = T[i][2];
            usm[k][c][i*4+0] = t0;
            usm[k][c][i*4+1] = 0.5f*(t0+t1+t2);
            usm[k][c][i*4+2] = 0.5f*(t0-t1+t2);
            usm[k][c][i*4+3] = t2;
        }
    }
    if (tid < KK) bsh[tid] = conv_b[n * KK + tid];
    __syncthreads();

    int pi = tid >> 4, pj = tid & 15;
    int y0 = 2 * pi, x0 = 2 * pj;

    float V[CC][16];
    #pragma unroll
    for (int c = 0; c < CC; c++) {
        float d[4][4];
        #pragma unroll
        for (int dy = 0; dy < 4; dy++) {
            int yy = y0 + dy - 1;
            #pragma unroll
            for (int dx = 0; dx < 4; dx++) {
                int xx = x0 + dx - 1;
                d[dy][dx] = (yy >= 0 && yy < PP && xx >= 0 && xx < PP)
                            ? xs[c][yy][xx] : 0.f;
            }
        }
        float tt[4][4];
        #pragma unroll
        for (int j = 0; j < 4; j++) {
            tt[0][j] = d[0][j] - d[2][j];
            tt[1][j] = d[1][j] + d[2][j];
            tt[2][j] = d[2][j] - d[1][j];
            tt[3][j] = d[1][j] - d[3][j];
        }
        #pragma unroll
        for (int i = 0; i < 4; i++) {
            V[c][i*4+0] = tt[i][0] - tt[i][2];
            V[c][i*4+1] = tt[i][1] + tt[i][2];
            V[c][i*4+2] = tt[i][2] - tt[i][1];
            V[c][i*4+3] = tt[i][1] - tt[i][3];
        }
    }

    size_t obase = (size_t)t * FLAT + tid;
    #pragma unroll 1
    for (int k = 0; k < KK; k++) {
        float M[16];
        #pragma unroll
        for (int c = 0; c < CC; c++) {
            const float4* up = (const float4*)usm[k][c];
            #pragma unroll
            for (int q = 0; q < 4; q++) {
                float4 u = up[q];
                if (c == 0) {
                    M[q*4+0] = V[0][q*4+0] * u.x;
                    M[q*4+1] = V[0][q*4+1] * u.y;
                    M[q*4+2] = V[0][q*4+2] * u.z;
                    M[q*4+3] = V[0][q*4+3] * u.w;
                } else {
                    M[q*4+0] = fmaf(V[c][q*4+0], u.x, M[q*4+0]);
                    M[q*4+1] = fmaf(V[c][q*4+1], u.y, M[q*4+1]);
                    M[q*4+2] = fmaf(V[c][q*4+2], u.z, M[q*4+2]);
                    M[q*4+3] = fmaf(V[c][q*4+3], u.w, M[q*4+3]);
                }
            }
        }
        float p0[4], p1[4];
        #pragma unroll
        for (int j = 0; j < 4; j++) {
            p0[j] = M[0*4+j] + M[1*4+j] + M[2*4+j];
            p1[j] = M[1*4+j] - M[2*4+j] - M[3*4+j];
        }
        float y00 = p0[0] + p0[1] + p0[2];
        float y01 = p0[1] - p0[2] - p0[3];
        float y10 = p1[0] + p1[1] + p1[2];
        float y11 = p1[1] - p1[2] - p1[3];
        float m = fmaxf(fmaxf(y00, y01), fmaxf(y10, y11));
        float v = fmaxf(m + bsh[k], 0.f);
        __nv_bfloat16 h = __float2bfloat16(v);
        g_fhi[obase + k * 256] = h;
        g_flo[obase + k * 256] = __float2bfloat16(v - __bfloat162float(h));
    }
}

// ============================================================
// Stage 2: lin1 via mma.sync bf16 (3-pass split, fp32 accum)
// grid (68, 2 m-half, 4: nhalf|khalf). block 256 = 8 warps.
// block tile: 64 graphs x 32 outs, K-range 2048 in chunks of 64.
// warp: n8 col (w&3), two m16 tiles ((w>>2)*2 +{0,1}).
// ============================================================
#define RA 72    // A smem row pitch (bf16) for bank stagger
#define RB 34    // B smem row pitch (bf16)

__global__ __launch_bounds__(256) void lin1_mma_kernel()
{
    __shared__ __nv_bfloat16 Ah[64 * RA];   // 9216 B
    __shared__ __nv_bfloat16 Al[64 * RA];
    __shared__ __nv_bfloat16 Bh[64 * RB];   // 4352 B
    __shared__ __nv_bfloat16 Bl[64 * RB];

    int n      = blockIdx.x;
    int gblk   = blockIdx.y * 64;            // graph base
    int oblk   = (blockIdx.z & 1) * 32;      // output base
    int khalf  = blockIdx.z >> 1;
    int fblk   = khalf * 2048;

    int tid  = threadIdx.x;
    int w    = tid >> 5;
    int lane = tid & 31;
    int gid  = lane >> 2;                    // groupID
    int tg   = lane & 3;

    int ncol  = (w & 3) * 8;                 // local n offset (0,8,16,24)
    int mt0   = (w >> 2) * 2;                // first m-tile (0 or 2)

    float c0[2][4];
    #pragma unroll
    for (int mi = 0; mi < 2; mi++)
        #pragma unroll
        for (int j = 0; j < 4; j++) c0[mi][j] = 0.f;

    const uint32_t* FH = (const uint32_t*)g_fhi;
    const uint32_t* FL = (const uint32_t*)g_flo;
    const uint32_t* WH = (const uint32_t*)g_whi;
    const uint32_t* WL = (const uint32_t*)g_wlo;
    uint32_t* AhU = (uint32_t*)Ah;
    uint32_t* AlU = (uint32_t*)Al;
    const unsigned short* Bh16 = (const unsigned short*)Bh;
    const unsigned short* Bl16 = (const unsigned short*)Bl;
    const unsigned short* Ah16 = (const unsigned short*)Ah;
    const unsigned short* Al16 = (const unsigned short*)Al;

    for (int fc = 0; fc < 2048; fc += 64) {
        __syncthreads();
        // load A tiles: 64 g x 64 f bf16 per plane = 2048 u32 each
        #pragma unroll
        for (int j = 0; j < 8; j++) {
            int e = tid + j * 256;           // u32 index
            int g = e >> 5;                  // row
            int cI = e & 31;                 // u32 col (f pair)
            size_t src = ((size_t)((gblk + g) * NN + n) * FLAT + fblk + fc) / 2 + cI;
            int dst = (g * RA + cI * 2) / 2; // u32 offset in smem
            AhU[dst] = FH[src];
            AlU[dst] = FL[src];
        }
        // load B tiles: 64 f x 32 o bf16 per plane = 1024 u32 each
        #pragma unroll
        for (int j = 0; j < 4; j++) {
            int e = tid + j * 256;
            int f = e >> 4;
            int cI = e & 15;                 // u32 col (o pair)
            size_t src = ((size_t)n * FLAT + fblk + fc + f) * FD / 2 + oblk / 2 + cI;
            ((uint32_t*)Bh)[(f * RB) / 2 + cI] = WH[src];
            ((uint32_t*)Bl)[(f * RB) / 2 + cI] = WL[src];
        }
        __syncthreads();

        #pragma unroll
        for (int ks = 0; ks < 4; ks++) {
            int kb = ks * 16;
            int oc = ncol + gid;
            int k0 = kb + tg * 2;
            uint32_t b0h = Bh16[k0 * RB + oc]       | ((uint32_t)Bh16[(k0 + 1) * RB + oc] << 16);
            uint32_t b1h = Bh16[(k0 + 8) * RB + oc] | ((uint32_t)Bh16[(k0 + 9) * RB + oc] << 16);
            uint32_t b0l = Bl16[k0 * RB + oc]       | ((uint32_t)Bl16[(k0 + 1) * RB + oc] << 16);
            uint32_t b1l = Bl16[(k0 + 8) * RB + oc] | ((uint32_t)Bl16[(k0 + 9) * RB + oc] << 16);

            #pragma unroll
            for (int mi = 0; mi < 2; mi++) {
                int gb = (mt0 + mi) * 16;
                int r0 = (gb + gid) * RA + k0;
                int r1 = (gb + gid + 8) * RA + k0;
                uint32_t a0h = *(const uint32_t*)&Ah16[r0];
                uint32_t a1h = *(const uint32_t*)&Ah16[r1];
                uint32_t a2h = *(const uint32_t*)&Ah16[r0 + 8];
                uint32_t a3h = *(const uint32_t*)&Ah16[r1 + 8];
                uint32_t a0l = *(const uint32_t*)&Al16[r0];
                uint32_t a1l = *(const uint32_t*)&Al16[r1];
                uint32_t a2l = *(const uint32_t*)&Al16[r0 + 8];
                uint32_t a3l = *(const uint32_t*)&Al16[r1 + 8];
                float* c = c0[mi];
                // hh
                asm volatile(
                    "mma.sync.aligned.m16n8k16.row.col.f32.bf16.bf16.f32 "
                    "{%0,%1,%2,%3}, {%4,%5,%6,%7}, {%8,%9}, {%0,%1,%2,%3};"
                    : "+f"(c[0]), "+f"(c[1]), "+f"(c[2]), "+f"(c[3])
                    : "r"(a0h), "r"(a1h), "r"(a2h), "r"(a3h), "r"(b0h), "r"(b1h));
                // hl
                asm volatile(
                    "mma.sync.aligned.m16n8k16.row.col.f32.bf16.bf16.f32 "
                    "{%0,%1,%2,%3}, {%4,%5,%6,%7}, {%8,%9}, {%0,%1,%2,%3};"
                    : "+f"(c[0]), "+f"(c[1]), "+f"(c[2]), "+f"(c[3])
                    : "r"(a0h), "r"(a1h), "r"(a2h), "r"(a3h), "r"(b0l), "r"(b1l));
                // lh
                asm volatile(
                    "mma.sync.aligned.m16n8k16.row.col.f32.bf16.bf16.f32 "
                    "{%0,%1,%2,%3}, {%4,%5,%6,%7}, {%8,%9}, {%0,%1,%2,%3};"
                    : "+f"(c[0]), "+f"(c[1]), "+f"(c[2]), "+f"(c[3])
                    : "r"(a0l), "r"(a1l), "r"(a2l), "r"(a3l), "r"(b0h), "r"(b1h));
            }
        }
    }

    // write partial sums (fp32)
    float* P = g_part[khalf];
    #pragma unroll
    for (int mi = 0; mi < 2; mi++) {
        int gA = gblk + (mt0 + mi) * 16 + gid;
        int o  = oblk + ncol + tg * 2;
        float* c = c0[mi];
        P[(size_t)(gA * NN + n) * FD + o]           = c[0];
        P[(size_t)(gA * NN + n) * FD + o + 1]       = c[1];
        P[(size_t)((gA + 8) * NN + n) * FD + o]     = c[2];
        P[(size_t)((gA + 8) * NN + n) * FD + o + 1] = c[3];
    }
}

// ============================================================
// Stage 3 (fused): combine partials + bias + relu -> feats,
// xw GEMM + degrees + CSR + aggregate + mean-pool + MLP head.
// ============================================================
struct GcnSmem {
    float wsm[FD * GH];
    float xw[NN * GH];
    union { float feats[NN * FD]; float h[NN * GH]; } u;
    int   s_src[EG];
    int   s_dst[EG];
    int   adj_src[EG];
    float adj_norm[EG];
    int   cnt[NN];
    int   startn[NN + 1];
    float dis[NN];
    float bsm[GH];
    float gsm[GH];
    float zsm[GH / 2];
};

__global__ __launch_bounds__(256) void gcn_head_kernel(
    const int* __restrict__ edge_index,
    const float* __restrict__ lin1_b,
    const float* __restrict__ gcn_w,
    const float* __restrict__ gcn_b,
    const float* __restrict__ w1, const float* __restrict__ b1,
    const float* __restrict__ w2, const float* __restrict__ b2,
    float* __restrict__ out)
{
    extern __shared__ char smem_raw[];
    GcnSmem* S = (GcnSmem*)smem_raw;
    int g = blockIdx.x;
    int tid = threadIdx.x;
    const int* srcA = edge_index + g * EG;
    const int* dstA = edge_index + BB * EG + g * EG;

    #pragma unroll
    for (int i = 0; i < FD * GH / 256; i++)
        S->wsm[tid + i * 256] = gcn_w[tid + i * 256];
    size_t goff = (size_t)g * NN * FD;
    for (int i = tid; i < NN * FD; i += 256)
        S->u.feats[i] = fmaxf(g_part[0][goff + i] + g_part[1][goff + i] + lin1_b[i], 0.f);
    for (int e = tid; e < EG; e += 256) {
        S->s_src[e] = srcA[e] - g * NN;
        S->s_dst[e] = dstA[e] - g * NN;
    }
    if (tid < GH) S->bsm[tid] = gcn_b[tid];
    __syncthreads();

    int ch = tid & 127, half = tid >> 7;
    for (int nd = half; nd < NN; nd += 2) {
        const float* fr = &S->u.feats[nd * FD];
        float acc = 0.f;
        #pragma unroll
        for (int c = 0; c < FD; c++)
            acc = fmaf(fr[c], S->wsm[c * GH + ch], acc);
        S->xw[nd * GH + ch] = acc;
    }

    if (tid < NN) {
        int c = 0;
        for (int e = 0; e < EG; e++) c += (S->s_dst[e] == tid);
        S->cnt[tid] = c;
        S->dis[tid] = rsqrtf((float)(c + 1));
    }
    __syncthreads();

    if (tid == 0) {
        int s = 0;
        for (int i = 0; i < NN; i++) { S->startn[i] = s; s += S->cnt[i]; }
        S->startn[NN] = s;
    }
    __syncthreads();

    if (tid < NN) {
        int p = S->startn[tid];
        float dn = S->dis[tid];
        for (int e = 0; e < EG; e++) {
            if (S->s_dst[e] == tid) {
                int sN = S->s_src[e];
                S->adj_src[p]  = sN;
                S->adj_norm[p] = S->dis[sN] * dn;
                p++;
            }
        }
    }
    __syncthreads();

    for (int nd = half; nd < NN; nd += 2) {
        float dn = S->dis[nd];
        float acc = dn * dn * S->xw[nd * GH + ch];
        int p1 = S->startn[nd + 1];
        for (int p = S->startn[nd]; p < p1; p++)
            acc = fmaf(S->adj_norm[p], S->xw[S->adj_src[p] * GH + ch], acc);
        S->u.h[nd * GH + ch] = fmaxf(acc + S->bsm[ch], 0.f);
    }
    __syncthreads();

    if (tid < GH) {
        float s = 0.f;
        #pragma unroll 4
        for (int i = 0; i < NN; i++) s += S->u.h[i * GH + tid];
        S->gsm[tid] = s * (1.0f / (float)NN);
    }
    __syncthreads();

    if (tid < GH / 2) {
        float acc = b1[tid];
        #pragma unroll
        for (int c = 0; c < GH; c++)
            acc = fmaf(S->gsm[c], w1[c * (GH / 2) + tid], acc);
        S->zsm[tid] = fmaxf(acc, 0.f);
    }
    __syncthreads();

    if (tid < OUTD) {
        float acc = b2[tid];
        for (int j = 0; j < GH / 2; j++)
            acc = fmaf(S->zsm[j], w2[j * OUTD + tid], acc);
        out[g * OUTD + tid] = acc;
    }
}

extern "C" void kernel_launch(void* const* d_in, const int* in_sizes, int n_in,
                              void* d_out, int out_size)
{
    const float* x        = (const float*)d_in[0];
    const int*   edge_idx = (const int*)  d_in[1];
    const float* conv_w   = (const float*)d_in[3];
    const float* conv_b   = (const float*)d_in[4];
    const float* lin1_w   = (const float*)d_in[5];
    const float* lin1_b   = (const float*)d_in[6];
    const float* gcn_w    = (const float*)d_in[7];
    const float* gcn_b    = (const float*)d_in[8];
    const float* mlp_w1   = (const float*)d_in[9];
    const float* mlp_b1   = (const float*)d_in[10];
    const float* mlp_w2   = (const float*)d_in[11];
    const float* mlp_b2   = (const float*)d_in[12];
    float* out = (float*)d_out;

    cudaFuncSetAttribute(gcn_head_kernel,
                         cudaFuncAttributeMaxDynamicSharedMemorySize,
                         (int)sizeof(GcnSmem));

    wsplit_kernel<<<(NN * FLAT * FD) / 2048, 256>>>(lin1_w);
    conv_pool_kernel<<<TT, 256>>>(x, conv_w, conv_b);
    lin1_mma_kernel<<<dim3(NN, 2, 4), 256>>>();
    gcn_head_kernel<<<BB, 256, sizeof(GcnSmem)>>>(
        edge_idx, lin1_b, gcn_w, gcn_b, mlp_w1, mlp_b1, mlp_w2, mlp_b2, out);
}

// round 7
// speedup vs baseline: 1.8086x; 1.4150x over previous
#include <cuda_runtime.h>
#include <cuda_bf16.h>
#include <cstdint>

#define BB 128          // graphs
#define NN 68           // landmarks per graph
#define CC 3            // input channels
#define PP 32           // patch
#define KK 16           // conv kernels
#define FD 64           // feature dim
#define GH 128          // gcn hidden
#define OUTD 2
#define EG (8*NN)       // 544 edges per graph
#define TT (BB*NN)      // 8704 nodes
#define FLAT (KK*(PP/2)*(PP/2))   // 4096
#define KSPLIT 4

// ---- scratch (allocation-free: device globals) ----
__device__ __nv_bfloat16 g_fhi[(size_t)TT * FLAT];        // activations hi [g*NN+n][f]
__device__ __nv_bfloat16 g_flo[(size_t)TT * FLAT];        // activations lo
__device__ __nv_bfloat16 g_whiT[(size_t)NN * FD * FLAT];  // W^T hi [n][o][f]
__device__ __nv_bfloat16 g_wloT[(size_t)NN * FD * FLAT];  // W^T lo
__device__ float g_part[KSPLIT][(size_t)BB * NN * FD];    // k-split partial sums
__device__ float g_xw[(size_t)TT * GH];

// ============================================================
// Stage 0: transpose+split lin1_w -> bf16 hi/lo [n][o][f]
// ============================================================
__global__ __launch_bounds__(256) void wsplitT_kernel(const float* __restrict__ lin1_w)
{
    int n = blockIdx.x, f0 = blockIdx.y * 64;
    __shared__ float tile[64][65];
    int tid = threadIdx.x;
    #pragma unroll
    for (int j = 0; j < 16; j++) {
        int e = tid + j * 256;
        int f = e >> 6, o = e & 63;
        tile[f][o] = lin1_w[((size_t)n * FLAT + f0 + f) * FD + o];
    }
    __syncthreads();
    #pragma unroll
    for (int j = 0; j < 8; j++) {
        int e = tid + j * 256;           // 64 o x 32 f-pairs
        int o = e >> 5, cu = e & 31;
        float w0 = tile[2 * cu][o], w1 = tile[2 * cu + 1][o];
        __nv_bfloat16 h0 = __float2bfloat16(w0);
        __nv_bfloat16 h1 = __float2bfloat16(w1);
        __nv_bfloat16 l0 = __float2bfloat16(w0 - __bfloat162float(h0));
        __nv_bfloat16 l1 = __float2bfloat16(w1 - __bfloat162float(h1));
        size_t dst = ((size_t)(n * FD + o) * FLAT + f0) + 2 * cu;
        g_whiT[dst] = h0; g_whiT[dst + 1] = h1;
        g_wloT[dst] = l0; g_wloT[dst + 1] = l1;
    }
}

// ============================================================
// Stage 1: Winograd F(2x2,3x3) conv + bias + relu + maxpool2x2
// ============================================================
__global__ __launch_bounds__(256) void conv_pool_kernel(
    const float* __restrict__ x,
    const float* __restrict__ conv_w,
    const float* __restrict__ conv_b)
{
    int t = blockIdx.x;
    int n = t % NN;
    __shared__ float xs[CC][PP][PP];
    __shared__ float usm[KK][CC][16];
    __shared__ float bsh[KK];

    int tid = threadIdx.x;
    const float4* xp4 = (const float4*)(x + (size_t)t * (CC * PP * PP));
    #pragma unroll
    for (int i = 0; i < 3; i++)
        ((float4*)xs)[tid + i * 256] = xp4[tid + i * 256];

    if (tid < KK * CC) {
        int k = tid / CC, c = tid % CC;
        const float* gw = conv_w + ((size_t)n * KK + k) * 27 + c * 9;
        float g0 = gw[0], g1 = gw[1], g2 = gw[2];
        float g3 = gw[3], g4 = gw[4], g5 = gw[5];
        float g6 = gw[6], g7 = gw[7], g8 = gw[8];
        float T[4][3];
        T[0][0] = g0;              T[0][1] = g1;              T[0][2] = g2;
        T[1][0] = 0.5f*(g0+g3+g6); T[1][1] = 0.5f*(g1+g4+g7); T[1][2] = 0.5f*(g2+g5+g8);
        T[2][0] = 0.5f*(g0-g3+g6); T[2][1] = 0.5f*(g1-g4+g7); T[2][2] = 0.5f*(g2-g5+g8);
        T[3][0] = g6;              T[3][1] = g7;              T[3][2] = g8;
        #pragma unroll
        for (int i = 0; i < 4; i++) {
            float t0 = T[i][0], t1 = T[i][1], t2 = T[i][2];
            usm[k][c][i*4+0] = t0;
            usm[k][c][i*4+1] = 0.5f*(t0+t1+t2);
            usm[k][c][i*4+2] = 0.5f*(t0-t1+t2);
            usm[k][c][i*4+3] = t2;
        }
    }
    if (tid < KK) bsh[tid] = conv_b[n * KK + tid];
    __syncthreads();

    int pi = tid >> 4, pj = tid & 15;
    int y0 = 2 * pi, x0 = 2 * pj;

    float V[CC][16];
    #pragma unroll
    for (int c = 0; c < CC; c++) {
        float d[4][4];
        #pragma unroll
        for (int dy = 0; dy < 4; dy++) {
            int yy = y0 + dy - 1;
            #pragma unroll
            for (int dx = 0; dx < 4; dx++) {
                int xx = x0 + dx - 1;
                d[dy][dx] = (yy >= 0 && yy < PP && xx >= 0 && xx < PP)
                            ? xs[c][yy][xx] : 0.f;
            }
        }
        float tt[4][4];
        #pragma unroll
        for (int j = 0; j < 4; j++) {
            tt[0][j] = d[0][j] - d[2][j];
            tt[1][j] = d[1][j] + d[2][j];
            tt[2][j] = d[2][j] - d[1][j];
            tt[3][j] = d[1][j] - d[3][j];
        }
        #pragma unroll
        for (int i = 0; i < 4; i++) {
            V[c][i*4+0] = tt[i][0] - tt[i][2];
            V[c][i*4+1] = tt[i][1] + tt[i][2];
            V[c][i*4+2] = tt[i][2] - tt[i][1];
            V[c][i*4+3] = tt[i][1] - tt[i][3];
        }
    }

    size_t obase = (size_t)t * FLAT + tid;
    #pragma unroll 1
    for (int k = 0; k < KK; k++) {
        float M[16];
        #pragma unroll
        for (int c = 0; c < CC; c++) {
            const float4* up = (const float4*)usm[k][c];
            #pragma unroll
            for (int q = 0; q < 4; q++) {
                float4 u = up[q];
                if (c == 0) {
                    M[q*4+0] = V[0][q*4+0] * u.x;
                    M[q*4+1] = V[0][q*4+1] * u.y;
                    M[q*4+2] = V[0][q*4+2] * u.z;
                    M[q*4+3] = V[0][q*4+3] * u.w;
                } else {
                    M[q*4+0] = fmaf(V[c][q*4+0], u.x, M[q*4+0]);
                    M[q*4+1] = fmaf(V[c][q*4+1], u.y, M[q*4+1]);
                    M[q*4+2] = fmaf(V[c][q*4+2], u.z, M[q*4+2]);
                    M[q*4+3] = fmaf(V[c][q*4+3], u.w, M[q*4+3]);
                }
            }
        }
        float p0[4], p1[4];
        #pragma unroll
        for (int j = 0; j < 4; j++) {
            p0[j] = M[0*4+j] + M[1*4+j] + M[2*4+j];
            p1[j] = M[1*4+j] - M[2*4+j] - M[3*4+j];
        }
        float y00 = p0[0] + p0[1] + p0[2];
        float y01 = p0[1] - p0[2] - p0[3];
        float y10 = p1[0] + p1[1] + p1[2];
        float y11 = p1[1] - p1[2] - p1[3];
        float m = fmaxf(fmaxf(y00, y01), fmaxf(y10, y11));
        float v = fmaxf(m + bsh[k], 0.f);
        __nv_bfloat16 h = __float2bfloat16(v);
        g_fhi[obase + k * 256] = h;
        g_flo[obase + k * 256] = __float2bfloat16(v - __bfloat162float(h));
    }
}

// ============================================================
// Stage 2: lin1 via mma.sync bf16 + ldmatrix (3-pass split)
// grid (68, KSPLIT). block 256 = 8 warps.
// block tile: M=128 graphs x N=64 outs, K 1024 in chunks of 64.
// warp: (wid&3)->32 m-rows, (wid>>2)->32 n-cols.
// smem: swizzled tiles, LDSM-friendly.
// ============================================================
#define SWB(row, byteoff) (((row) * 128) + ((byteoff) ^ (((row) & 7) << 4)))
#define L1_AH 0
#define L1_AL 16384
#define L1_BH 32768
#define L1_BL 40960
#define L1_TOTAL 49152

__device__ __forceinline__ uint32_t smem_u32(const void* p) {
    uint32_t a;
    asm("{ .reg .u64 t; cvta.to.shared.u64 t, %1; cvt.u32.u64 %0, t; }" : "=r"(a) : "l"(p));
    return a;
}
__device__ __forceinline__ void ldsm_x4(uint32_t& r0, uint32_t& r1, uint32_t& r2, uint32_t& r3, uint32_t a) {
    asm volatile("ldmatrix.sync.aligned.m8n8.x4.shared.b16 {%0,%1,%2,%3}, [%4];"
                 : "=r"(r0), "=r"(r1), "=r"(r2), "=r"(r3) : "r"(a));
}
__device__ __forceinline__ void ldsm_x2(uint32_t& r0, uint32_t& r1, uint32_t a) {
    asm volatile("ldmatrix.sync.aligned.m8n8.x2.shared.b16 {%0,%1}, [%2];"
                 : "=r"(r0), "=r"(r1) : "r"(a));
}
#define MMA16816(c, a0, a1, a2, a3, b0, b1) \
    asm volatile("mma.sync.aligned.m16n8k16.row.col.f32.bf16.bf16.f32 " \
        "{%0,%1,%2,%3}, {%4,%5,%6,%7}, {%8,%9}, {%0,%1,%2,%3};" \
        : "+f"((c)[0]), "+f"((c)[1]), "+f"((c)[2]), "+f"((c)[3]) \
        : "r"(a0), "r"(a1), "r"(a2), "r"(a3), "r"(b0), "r"(b1))

__global__ __launch_bounds__(256) void lin1_mma_kernel()
{
    extern __shared__ char sm[];
    uint32_t smb = smem_u32(sm);

    int n  = blockIdx.x;
    int kh = blockIdx.y;
    int fbase = kh * (FLAT / KSPLIT);    // 1024 per split

    int tid  = threadIdx.x;
    int wid  = tid >> 5;
    int lane = tid & 31;
    int wm   = (wid & 3) * 32;           // warp m base (graphs)
    int wn   = (wid >> 2) * 32;          // warp n base (outs)

    float acc[2][4][4];                  // [mtile][ntile][frag]
    #pragma unroll
    for (int mt = 0; mt < 2; mt++)
        #pragma unroll
        for (int nt = 0; nt < 4; nt++)
            #pragma unroll
            for (int q = 0; q < 4; q++) acc[mt][nt][q] = 0.f;

    const uint4* FH = (const uint4*)g_fhi;
    const uint4* FL = (const uint4*)g_flo;
    const uint4* WH = (const uint4*)g_whiT;
    const uint4* WL = (const uint4*)g_wloT;

    // precomputed ldmatrix lane addresses (byte offsets within tiles)
    int arow = lane & 15;                // A: local row within 16
    int acolb = (lane >> 4) * 16;        // A: 0 or 16 bytes (k-half)
    int brow = lane & 7;                 // B: local row within 8
    int bcolb = ((lane >> 3) & 1) * 16;  // B: k-half bytes

    #pragma unroll 1
    for (int ci = 0; ci < (FLAT / KSPLIT) / 64; ci++) {
        int fc = fbase + ci * 64;
        __syncthreads();
        // A: 128 g x 64 f, both planes. 1024 uint4 per plane.
        #pragma unroll
        for (int j = 0; j < 4; j++) {
            int e = tid + j * 256;
            int row = e >> 3, q = e & 7;
            size_t src = (((size_t)(row * NN + n) * FLAT + fc) >> 3) + q;
            uint32_t d = SWB(row, q * 16);
            *(uint4*)(sm + L1_AH + d) = FH[src];
            *(uint4*)(sm + L1_AL + d) = FL[src];
        }
        // B: 64 o x 64 f, both planes. 512 uint4 per plane.
        #pragma unroll
        for (int j = 0; j < 2; j++) {
            int e = tid + j * 256;
            int row = e >> 3, q = e & 7;
            size_t src = (((size_t)(n * FD + row) * FLAT + fc) >> 3) + q;
            uint32_t d = SWB(row, q * 16);
            *(uint4*)(sm + L1_BH + d) = WH[src];
            *(uint4*)(sm + L1_BL + d) = WL[src];
        }
        __syncthreads();

        #pragma unroll
        for (int ks = 0; ks < 4; ks++) {
            int kb = ks * 32;            // byte offset of k-step (16 bf16)
            uint32_t ah[2][4], al[2][4];
            #pragma unroll
            for (int mt = 0; mt < 2; mt++) {
                int row = wm + mt * 16 + arow;
                uint32_t ad = SWB(row, kb + acolb);
                ldsm_x4(ah[mt][0], ah[mt][1], ah[mt][2], ah[mt][3], smb + L1_AH + ad);
                ldsm_x4(al[mt][0], al[mt][1], al[mt][2], al[mt][3], smb + L1_AL + ad);
            }
            uint32_t bh[4][2], bl[4][2];
            #pragma unroll
            for (int nt = 0; nt < 4; nt++) {
                int row = wn + nt * 8 + brow;
                uint32_t bd = SWB(row, kb + bcolb);
                ldsm_x2(bh[nt][0], bh[nt][1], smb + L1_BH + bd);
                ldsm_x2(bl[nt][0], bl[nt][1], smb + L1_BL + bd);
            }
            #pragma unroll
            for (int mt = 0; mt < 2; mt++)
                #pragma unroll
                for (int nt = 0; nt < 4; nt++) {
                    MMA16816(acc[mt][nt], ah[mt][0], ah[mt][1], ah[mt][2], ah[mt][3],
                             bh[nt][0], bh[nt][1]);                     // hh
                    MMA16816(acc[mt][nt], ah[mt][0], ah[mt][1], ah[mt][2], ah[mt][3],
                             bl[nt][0], bl[nt][1]);                     // hl
                    MMA16816(acc[mt][nt], al[mt][0], al[mt][1], al[mt][2], al[mt][3],
                             bh[nt][0], bh[nt][1]);                     // lh
                }
        }
    }

    // epilogue: c0,c1 at (row, col), c2,c3 at (row+8, col)
    float* P = g_part[kh];
    int r0 = lane >> 2, c0 = (lane & 3) * 2;
    #pragma unroll
    for (int mt = 0; mt < 2; mt++) {
        int g0 = wm + mt * 16 + r0;
        #pragma unroll
        for (int nt = 0; nt < 4; nt++) {
            int o = wn + nt * 8 + c0;
            float* p0 = &P[(size_t)(g0 * NN + n) * FD + o];
            float* p1 = &P[(size_t)((g0 + 8) * NN + n) * FD + o];
            p0[0] = acc[mt][nt][0]; p0[1] = acc[mt][nt][1];
            p1[0] = acc[mt][nt][2]; p1[1] = acc[mt][nt][3];
        }
    }
}

// ============================================================
// Stage 3: feats = relu(sum parts + bias); xw = feats @ gcn_w
// ============================================================
__global__ __launch_bounds__(512) void gcn_xw_kernel(
    const float* __restrict__ lin1_b, const float* __restrict__ gcn_w)
{
    int t0 = blockIdx.x * 4;
    __shared__ float wsm[FD * GH];       // 32 KB
    __shared__ float fsm[4 * FD];
    int tid = threadIdx.x;
    #pragma unroll
    for (int i = 0; i < 16; i++)
        wsm[tid + i * 512] = gcn_w[tid + i * 512];
    if (tid < 4 * FD) {
        int nd = tid >> 6, c = tid & 63;
        int t = t0 + nd, n = t % NN;
        size_t ix = (size_t)t * FD + c;
        float s = g_part[0][ix] + g_part[1][ix] + g_part[2][ix] + g_part[3][ix];
        fsm[tid] = fmaxf(s + lin1_b[n * FD + c], 0.f);
    }
    __syncthreads();

    int j = tid & 127, nd = tid >> 7;
    float acc = 0.f;
    #pragma unroll
    for (int c = 0; c < FD; c++)
        acc = fmaf(fsm[nd * FD + c], wsm[c * GH + j], acc);
    g_xw[(size_t)(t0 + nd) * GH + j] = acc;
}

// ============================================================
// Stage 4: per-graph dense-A GCN aggregate + pool + MLP head
// ============================================================
struct HeadSmem {
    float xw[NN * GH];                   // 34816
    union { int cnt[NN * NN]; float Af[NN * NN]; } a;  // 18496
    float dis[NN];
    float bsm[GH];
    float gsm[GH];
    float zsm[GH / 2];
    float pool[2 * GH];
};

__global__ __launch_bounds__(256) void gcn_head_kernel(
    const int* __restrict__ edge_index,
    const float* __restrict__ gcn_b,
    const float* __restrict__ w1, const float* __restrict__ b1,
    const float* __restrict__ w2, const float* __restrict__ b2,
    float* __restrict__ out)
{
    extern __shared__ char smem_raw[];
    HeadSmem* S = (HeadSmem*)smem_raw;
    int g = blockIdx.x;
    int tid = threadIdx.x;
    const int* srcA = edge_index + g * EG;
    const int* dstA = edge_index + BB * EG + g * EG;

    const float4* xws = (const float4*)(g_xw + (size_t)g * NN * GH);
    #pragma unroll
    for (int i = 0; i < 9; i++) {
        int e = tid + i * 256;
        if (e < NN * GH / 4) ((float4*)S->xw)[e] = xws[e];
    }
    for (int i = tid; i < NN * NN; i += 256) S->a.cnt[i] = 0;
    if (tid < GH) S->bsm[tid] = gcn_b[tid];
    __syncthreads();

    // count matrix (int atomics = deterministic)
    for (int e = tid; e < EG; e += 256) {
        int s = srcA[e] - g * NN;
        int d = dstA[e] - g * NN;
        atomicAdd(&S->a.cnt[d * NN + s], 1);
    }
    __syncthreads();

    if (tid < NN) {
        int deg = 1;                     // self loop
        for (int s = 0; s < NN; s++) deg += S->a.cnt[tid * NN + s];
        S->dis[tid] = rsqrtf((float)deg);
    }
    __syncthreads();

    // convert counts -> normalized float adjacency (in place)
    for (int i = tid; i < NN * NN; i += 256) {
        int d = i / NN, s = i - d * NN;
        float c = (float)S->a.cnt[i];
        float v = c * S->dis[d] * S->dis[s];
        if (d == s) v += S->dis[d] * S->dis[d];
        S->a.Af[i] = v;
    }
    __syncthreads();

    // dense aggregate + fused mean pool
    int ch = tid & 127, half = tid >> 7;
    float pacc = 0.f;
    for (int nd = half; nd < NN; nd += 2) {
        const float* arow = &S->a.Af[nd * NN];
        float accv = 0.f;
        #pragma unroll 4
        for (int s = 0; s < NN; s++)
            accv = fmaf(arow[s], S->xw[s * GH + ch], accv);
        pacc += fmaxf(accv + S->bsm[ch], 0.f);
    }
    S->pool[half * GH + ch] = pacc;
    __syncthreads();

    if (tid < GH)
        S->gsm[tid] = (S->pool[tid] + S->pool[GH + tid]) * (1.0f / (float)NN);
    __syncthreads();

    if (tid < GH / 2) {
        float accv = b1[tid];
        #pragma unroll
        for (int c = 0; c < GH; c++)
            accv = fmaf(S->gsm[c], w1[c * (GH / 2) + tid], accv);
        S->zsm[tid] = fmaxf(accv, 0.f);
    }
    __syncthreads();

    if (tid < OUTD) {
        float accv = b2[tid];
        for (int j = 0; j < GH / 2; j++)
            accv = fmaf(S->zsm[j], w2[j * OUTD + tid], accv);
        out[g * OUTD + tid] = accv;
    }
}

extern "C" void kernel_launch(void* const* d_in, const int* in_sizes, int n_in,
                              void* d_out, int out_size)
{
    const float* x        = (const float*)d_in[0];
    const int*   edge_idx = (const int*)  d_in[1];
    const float* conv_w   = (const float*)d_in[3];
    const float* conv_b   = (const float*)d_in[4];
    const float* lin1_w   = (const float*)d_in[5];
    const float* lin1_b   = (const float*)d_in[6];
    const float* gcn_w    = (const float*)d_in[7];
    const float* gcn_b    = (const float*)d_in[8];
    const float* mlp_w1   = (const float*)d_in[9];
    const float* mlp_b1   = (const float*)d_in[10];
    const float* mlp_w2   = (const float*)d_in[11];
    const float* mlp_b2   = (const float*)d_in[12];
    float* out = (float*)d_out;

    cudaFuncSetAttribute(lin1_mma_kernel,
                         cudaFuncAttributeMaxDynamicSharedMemorySize, L1_TOTAL);
    cudaFuncSetAttribute(gcn_head_kernel,
                         cudaFuncAttributeMaxDynamicSharedMemorySize,
                         (int)sizeof(HeadSmem));

    wsplitT_kernel<<<dim3(NN, FLAT / 64), 256>>>(lin1_w);
    conv_pool_kernel<<<TT, 256>>>(x, conv_w, conv_b);
    lin1_mma_kernel<<<dim3(NN, KSPLIT), 256, L1_TOTAL>>>();
    gcn_xw_kernel<<<TT / 4, 512>>>(lin1_b, gcn_w);
    gcn_head_kernel<<<BB, 256, sizeof(HeadSmem)>>>(
        edge_idx, gcn_b, mlp_w1, mlp_b1, mlp_w2, mlp_b2, out);
}

// round 8
// speedup vs baseline: 2.0201x; 1.1170x over previous
#include <cuda_runtime.h>
#include <cuda_bf16.h>
#include <cstdint>

#define BB 128          // graphs
#define NN 68           // landmarks per graph
#define CC 3            // input channels
#define PP 32           // patch
#define KK 16           // conv kernels
#define FD 64           // feature dim
#define GH 128          // gcn hidden
#define OUTD 2
#define EG (8*NN)       // 544 edges per graph
#define TT (BB*NN)      // 8704 nodes
#define FLAT (KK*(PP/2)*(PP/2))   // 4096
#define KSPLIT 4

typedef unsigned long long u64;

// ---- scratch (allocation-free: device globals) ----
__device__ float g_flat[(size_t)TT * FLAT];               // fp32 activations
__device__ float g_part[KSPLIT][(size_t)BB * NN * FD];    // k-split partial sums
__device__ float g_xw[(size_t)TT * GH];

// ---- f32x2 helpers ----
__device__ __forceinline__ u64 pk2(float lo, float hi) {
    u64 r; asm("mov.b64 %0, {%1, %2};" : "=l"(r) : "f"(lo), "f"(hi)); return r;
}
__device__ __forceinline__ void upk2(u64 v, float& lo, float& hi) {
    asm("mov.b64 {%0, %1}, %2;" : "=f"(lo), "=f"(hi) : "l"(v));
}
__device__ __forceinline__ u64 fma2(u64 a, u64 b, u64 c) {
    u64 d; asm("fma.rn.f32x2 %0, %1, %2, %3;" : "=l"(d) : "l"(a), "l"(b), "l"(c)); return d;
}
__device__ __forceinline__ u64 mul2(u64 a, u64 b) {
    u64 d; asm("mul.rn.f32x2 %0, %1, %2;" : "=l"(d) : "l"(a), "l"(b)); return d;
}
__device__ __forceinline__ u64 add2(u64 a, u64 b) {
    u64 d; asm("add.rn.f32x2 %0, %1, %2;" : "=l"(d) : "l"(a), "l"(b)); return d;
}
#define NEG2(v) ((v) ^ 0x8000000080000000ULL)

// bf16 pack: lower 16 bits = lo element
__device__ __forceinline__ uint32_t bf2(float lo, float hi) {
    uint32_t r; asm("cvt.rn.bf16x2.f32 %0, %1, %2;" : "=r"(r) : "f"(hi), "f"(lo)); return r;
}

// ============================================================
// Stage 1: Winograd F(2x2,3x3) conv + bias + relu + maxpool2x2
// f32x2-packed point dimension; fp32 output
// ============================================================
__global__ __launch_bounds__(256) void conv_pool_kernel(
    const float* __restrict__ x,
    const float* __restrict__ conv_w,
    const float* __restrict__ conv_b)
{
    int t = blockIdx.x;
    int n = t % NN;
    __shared__ float xs[CC][PP][PP];
    __shared__ __align__(16) float usm[KK][CC][16];
    __shared__ float bsh[KK];

    int tid = threadIdx.x;
    const float4* xp4 = (const float4*)(x + (size_t)t * (CC * PP * PP));
    #pragma unroll
    for (int i = 0; i < 3; i++)
        ((float4*)xs)[tid + i * 256] = xp4[tid + i * 256];

    if (tid < KK * CC) {
        int k = tid / CC, c = tid % CC;
        const float* gw = conv_w + ((size_t)n * KK + k) * 27 + c * 9;
        float g0 = gw[0], g1 = gw[1], g2 = gw[2];
        float g3 = gw[3], g4 = gw[4], g5 = gw[5];
        float g6 = gw[6], g7 = gw[7], g8 = gw[8];
        float T[4][3];
        T[0][0] = g0;              T[0][1] = g1;              T[0][2] = g2;
        T[1][0] = 0.5f*(g0+g3+g6); T[1][1] = 0.5f*(g1+g4+g7); T[1][2] = 0.5f*(g2+g5+g8);
        T[2][0] = 0.5f*(g0-g3+g6); T[2][1] = 0.5f*(g1-g4+g7); T[2][2] = 0.5f*(g2-g5+g8);
        T[3][0] = g6;              T[3][1] = g7;              T[3][2] = g8;
        #pragma unroll
        for (int i = 0; i < 4; i++) {
            float t0 = T[i][0], t1 = T[i][1], t2 = T[i][2];
            usm[k][c][i*4+0] = t0;
            usm[k][c][i*4+1] = 0.5f*(t0+t1+t2);
            usm[k][c][i*4+2] = 0.5f*(t0-t1+t2);
            usm[k][c][i*4+3] = t2;
        }
    }
    if (tid < KK) bsh[tid] = conv_b[n * KK + tid];
    __syncthreads();

    int pi = tid >> 4, pj = tid & 15;
    int y0 = 2 * pi, x0 = 2 * pj;

    // V = B^T d B per channel, packed into point-pairs VP[c][8]
    u64 VP[CC][8];
    #pragma unroll
    for (int c = 0; c < CC; c++) {
        float d[4][4];
        #pragma unroll
        for (int dy = 0; dy < 4; dy++) {
            int yy = y0 + dy - 1;
            #pragma unroll
            for (int dx = 0; dx < 4; dx++) {
                int xx = x0 + dx - 1;
                d[dy][dx] = (yy >= 0 && yy < PP && xx >= 0 && xx < PP)
                            ? xs[c][yy][xx] : 0.f;
            }
        }
        float tt[4][4];
        #pragma unroll
        for (int j = 0; j < 4; j++) {
            tt[0][j] = d[0][j] - d[2][j];
            tt[1][j] = d[1][j] + d[2][j];
            tt[2][j] = d[2][j] - d[1][j];
            tt[3][j] = d[1][j] - d[3][j];
        }
        #pragma unroll
        for (int i = 0; i < 4; i++) {
            float v0 = tt[i][0] - tt[i][2];
            float v1 = tt[i][1] + tt[i][2];
            float v2 = tt[i][2] - tt[i][1];
            float v3 = tt[i][1] - tt[i][3];
            VP[c][i*2 + 0] = pk2(v0, v1);
            VP[c][i*2 + 1] = pk2(v2, v3);
        }
    }

    float* outp = &g_flat[(size_t)t * FLAT + tid];
    #pragma unroll 1
    for (int k = 0; k < KK; k++) {
        u64 MP[8];
        {
            const ulonglong2* u0 = (const ulonglong2*)usm[k][0];
            #pragma unroll
            for (int q = 0; q < 4; q++) {
                ulonglong2 uv = u0[q];
                MP[q*2]   = mul2(VP[0][q*2],   uv.x);
                MP[q*2+1] = mul2(VP[0][q*2+1], uv.y);
            }
            #pragma unroll
            for (int c = 1; c < CC; c++) {
                const ulonglong2* uc = (const ulonglong2*)usm[k][c];
                #pragma unroll
                for (int q = 0; q < 4; q++) {
                    ulonglong2 uv = uc[q];
                    MP[q*2]   = fma2(VP[c][q*2],   uv.x, MP[q*2]);
                    MP[q*2+1] = fma2(VP[c][q*2+1], uv.y, MP[q*2+1]);
                }
            }
        }
        // A^T M A, packed columns (MP[row*2+cp] covers cols 2cp,2cp+1)
        u64 p0a = add2(add2(MP[0], MP[2]), MP[4]);
        u64 p0b = add2(add2(MP[1], MP[3]), MP[5]);
        u64 t0  = add2(MP[4], MP[6]);
        u64 t1  = add2(MP[5], MP[7]);
        u64 p1a = add2(MP[2], NEG2(t0));
        u64 p1b = add2(MP[3], NEG2(t1));
        float q0, q1, q2, q3, r0, r1, r2, r3;
        upk2(p0a, q0, q1); upk2(p0b, q2, q3);
        upk2(p1a, r0, r1); upk2(p1b, r2, r3);
        float y00 = q0 + q1 + q2;
        float y01 = q1 - q2 - q3;
        float y10 = r0 + r1 + r2;
        float y11 = r1 - r2 - r3;
        float m = fmaxf(fmaxf(y00, y01), fmaxf(y10, y11));
        outp[k * 256] = fmaxf(m + bsh[k], 0.f);
    }
}

// ============================================================
// Stage 2: lin1 via mma.sync bf16 + ldmatrix (3-pass split),
// with INLINE fp32 -> bf16 hi/lo split in the smem loaders.
// grid (68, KSPLIT); block 256 = 8 warps.
// ============================================================
#define SWB(row, byteoff) (((row) * 128) + ((byteoff) ^ (((row) & 7) << 4)))
#define L1_AH 0
#define L1_AL 16384
#define L1_BH 32768
#define L1_BL 40960
#define L1_TOTAL 49152

__device__ __forceinline__ uint32_t smem_u32(const void* p) {
    uint32_t a;
    asm("{ .reg .u64 t; cvta.to.shared.u64 t, %1; cvt.u32.u64 %0, t; }" : "=r"(a) : "l"(p));
    return a;
}
__device__ __forceinline__ void ldsm_x4(uint32_t& r0, uint32_t& r1, uint32_t& r2, uint32_t& r3, uint32_t a) {
    asm volatile("ldmatrix.sync.aligned.m8n8.x4.shared.b16 {%0,%1,%2,%3}, [%4];"
                 : "=r"(r0), "=r"(r1), "=r"(r2), "=r"(r3) : "r"(a));
}
__device__ __forceinline__ void ldsm_x2(uint32_t& r0, uint32_t& r1, uint32_t a) {
    asm volatile("ldmatrix.sync.aligned.m8n8.x2.shared.b16 {%0,%1}, [%2];"
                 : "=r"(r0), "=r"(r1) : "r"(a));
}
#define MMA16816(c, a0, a1, a2, a3, b0, b1) \
    asm volatile("mma.sync.aligned.m16n8k16.row.col.f32.bf16.bf16.f32 " \
        "{%0,%1,%2,%3}, {%4,%5,%6,%7}, {%8,%9}, {%0,%1,%2,%3};" \
        : "+f"((c)[0]), "+f"((c)[1]), "+f"((c)[2]), "+f"((c)[3]) \
        : "r"(a0), "r"(a1), "r"(a2), "r"(a3), "r"(b0), "r"(b1))

__global__ __launch_bounds__(256) void lin1_mma_kernel(const float* __restrict__ lin1_w)
{
    extern __shared__ char sm[];
    uint32_t smb = smem_u32(sm);

    int n  = blockIdx.x;
    int kh = blockIdx.y;
    int fbase = kh * (FLAT / KSPLIT);    // 1024 per split

    int tid  = threadIdx.x;
    int wid  = tid >> 5;
    int lane = tid & 31;
    int wm   = (wid & 3) * 32;           // warp m base (graphs)
    int wn   = (wid >> 2) * 32;          // warp n base (outs)

    float acc[2][4][4];
    #pragma unroll
    for (int mt = 0; mt < 2; mt++)
        #pragma unroll
        for (int nt = 0; nt < 4; nt++)
            #pragma unroll
            for (int q = 0; q < 4; q++) acc[mt][nt][q] = 0.f;

    int arow = lane & 15;
    int acolb = (lane >> 4) * 16;
    int brow = lane & 7;
    int bcolb = ((lane >> 3) & 1) * 16;

    // B loader geometry: thread handles (o = tid&63, f segment (tid>>6)*16)
    int bo = tid & 63;
    int bfs = (tid >> 6) * 16;

    #pragma unroll 1
    for (int ci = 0; ci < (FLAT / KSPLIT) / 64; ci++) {
        int fc = fbase + ci * 64;
        __syncthreads();
        // A: 128 g x 64 f fp32 -> split hi/lo bf16, swizzled. 2048 float4.
        #pragma unroll
        for (int j = 0; j < 8; j++) {
            int e = tid + j * 256;
            int row = e >> 4, q = e & 15;    // row = graph, q = float4 idx
            float4 v = ((const float4*)g_flat)[(((size_t)(row * NN + n) * FLAT + fc) >> 2) + q];
            uint32_t h0 = bf2(v.x, v.y), h1 = bf2(v.z, v.w);
            float hx = __bfloat162float(__ushort_as_bfloat16((unsigned short)(h0 & 0xFFFF)));
            float hy = __bfloat162float(__ushort_as_bfloat16((unsigned short)(h0 >> 16)));
            float hz = __bfloat162float(__ushort_as_bfloat16((unsigned short)(h1 & 0xFFFF)));
            float hw = __bfloat162float(__ushort_as_bfloat16((unsigned short)(h1 >> 16)));
            uint32_t l0 = bf2(v.x - hx, v.y - hy), l1 = bf2(v.z - hz, v.w - hw);
            uint32_t d = SWB(row, q * 8);
            *(uint2*)(sm + L1_AH + d) = make_uint2(h0, h1);
            *(uint2*)(sm + L1_AL + d) = make_uint2(l0, l1);
        }
        // B: read W fp32 [f][o], transpose+split into smem rows [o][f].
        {
            const float* wsrc = lin1_w + ((size_t)n * FLAT + fc + bfs) * FD + bo;
            float wv[16];
            #pragma unroll
            for (int i = 0; i < 16; i++) wv[i] = wsrc[i * FD];
            #pragma unroll
            for (int j = 0; j < 4; j++) {
                uint32_t h0 = bf2(wv[4*j], wv[4*j+1]);
                uint32_t h1 = bf2(wv[4*j+2], wv[4*j+3]);
                float h0x = __bfloat162float(__ushort_as_bfloat16((unsigned short)(h0 & 0xFFFF)));
                float h0y = __bfloat162float(__ushort_as_bfloat16((unsigned short)(h0 >> 16)));
                float h1x = __bfloat162float(__ushort_as_bfloat16((unsigned short)(h1 & 0xFFFF)));
                float h1y = __bfloat162float(__ushort_as_bfloat16((unsigned short)(h1 >> 16)));
                uint32_t l0 = bf2(wv[4*j] - h0x, wv[4*j+1] - h0y);
                uint32_t l1 = bf2(wv[4*j+2] - h1x, wv[4*j+3] - h1y);
                uint32_t d = SWB(bo, (bfs + 4*j) * 2);
                *(uint2*)(sm + L1_BH + d) = make_uint2(h0, h1);
                *(uint2*)(sm + L1_BL + d) = make_uint2(l0, l1);
            }
        }
        __syncthreads();

        #pragma unroll
        for (int ks = 0; ks < 4; ks++) {
            int kb = ks * 32;
            uint32_t ah[2][4], al[2][4];
            #pragma unroll
            for (int mt = 0; mt < 2; mt++) {
                int row = wm + mt * 16 + arow;
                uint32_t ad = SWB(row, kb + acolb);
                ldsm_x4(ah[mt][0], ah[mt][1], ah[mt][2], ah[mt][3], smb + L1_AH + ad);
                ldsm_x4(al[mt][0], al[mt][1], al[mt][2], al[mt][3], smb + L1_AL + ad);
            }
            uint32_t bh[4][2], bl[4][2];
            #pragma unroll
            for (int nt = 0; nt < 4; nt++) {
                int row = wn + nt * 8 + brow;
                uint32_t bd = SWB(row, kb + bcolb);
                ldsm_x2(bh[nt][0], bh[nt][1], smb + L1_BH + bd);
                ldsm_x2(bl[nt][0], bl[nt][1], smb + L1_BL + bd);
            }
            #pragma unroll
            for (int mt = 0; mt < 2; mt++)
                #pragma unroll
                for (int nt = 0; nt < 4; nt++) {
                    MMA16816(acc[mt][nt], ah[mt][0], ah[mt][1], ah[mt][2], ah[mt][3],
                             bh[nt][0], bh[nt][1]);                     // hh
                    MMA16816(acc[mt][nt], ah[mt][0], ah[mt][1], ah[mt][2], ah[mt][3],
                             bl[nt][0], bl[nt][1]);                     // hl
                    MMA16816(acc[mt][nt], al[mt][0], al[mt][1], al[mt][2], al[mt][3],
                             bh[nt][0], bh[nt][1]);                     // lh
                }
        }
    }

    float* P = g_part[kh];
    int r0 = lane >> 2, c0 = (lane & 3) * 2;
    #pragma unroll
    for (int mt = 0; mt < 2; mt++) {
        int g0 = wm + mt * 16 + r0;
        #pragma unroll
        for (int nt = 0; nt < 4; nt++) {
            int o = wn + nt * 8 + c0;
            float* p0 = &P[(size_t)(g0 * NN + n) * FD + o];
            float* p1 = &P[(size_t)((g0 + 8) * NN + n) * FD + o];
            p0[0] = acc[mt][nt][0]; p0[1] = acc[mt][nt][1];
            p1[0] = acc[mt][nt][2]; p1[1] = acc[mt][nt][3];
        }
    }
}

// ============================================================
// Stage 3: feats = relu(sum parts + bias); xw = feats @ gcn_w
// 4 independent accumulator chains
// ============================================================
__global__ __launch_bounds__(512) void gcn_xw_kernel(
    const float* __restrict__ lin1_b, const float* __restrict__ gcn_w)
{
    int t0 = blockIdx.x * 4;
    __shared__ float wsm[FD * GH];
    __shared__ float fsm[4 * FD];
    int tid = threadIdx.x;
    #pragma unroll
    for (int i = 0; i < 16; i++)
        wsm[tid + i * 512] = gcn_w[tid + i * 512];
    if (tid < 4 * FD) {
        int nd = tid >> 6, c = tid & 63;
        int t = t0 + nd, n = t % NN;
        size_t ix = (size_t)t * FD + c;
        float s = g_part[0][ix] + g_part[1][ix] + g_part[2][ix] + g_part[3][ix];
        fsm[tid] = fmaxf(s + lin1_b[n * FD + c], 0.f);
    }
    __syncthreads();

    int j = tid & 127, nd = tid >> 7;
    float a0 = 0.f, a1 = 0.f, a2 = 0.f, a3 = 0.f;
    const float* fr = &fsm[nd * FD];
    #pragma unroll
    for (int c = 0; c < FD; c += 4) {
        a0 = fmaf(fr[c],     wsm[c * GH + j],       a0);
        a1 = fmaf(fr[c + 1], wsm[(c + 1) * GH + j], a1);
        a2 = fmaf(fr[c + 2], wsm[(c + 2) * GH + j], a2);
        a3 = fmaf(fr[c + 3], wsm[(c + 3) * GH + j], a3);
    }
    g_xw[(size_t)(t0 + nd) * GH + j] = (a0 + a1) + (a2 + a3);
}

// ============================================================
// Stage 4: per-graph dense-A GCN aggregate + pool + MLP head
// ============================================================
struct HeadSmem {
    float xw[NN * GH];
    union { int cnt[NN * NN]; float Af[NN * NN]; } a;
    float dis[NN];
    float bsm[GH];
    float gsm[GH];
    float zsm[GH / 2];
    float pool[2 * GH];
};

__global__ __launch_bounds__(256) void gcn_head_kernel(
    const int* __restrict__ edge_index,
    const float* __restrict__ gcn_b,
    const float* __restrict__ w1, const float* __restrict__ b1,
    const float* __restrict__ w2, const float* __restrict__ b2,
    float* __restrict__ out)
{
    extern __shared__ char smem_raw[];
    HeadSmem* S = (HeadSmem*)smem_raw;
    int g = blockIdx.x;
    int tid = threadIdx.x;
    const int* srcA = edge_index + g * EG;
    const int* dstA = edge_index + BB * EG + g * EG;

    const float4* xws = (const float4*)(g_xw + (size_t)g * NN * GH);
    #pragma unroll
    for (int i = 0; i < 9; i++) {
        int e = tid + i * 256;
        if (e < NN * GH / 4) ((float4*)S->xw)[e] = xws[e];
    }
    for (int i = tid; i < NN * NN; i += 256) S->a.cnt[i] = 0;
    if (tid < GH) S->bsm[tid] = gcn_b[tid];
    __syncthreads();

    for (int e = tid; e < EG; e += 256) {
        int s = srcA[e] - g * NN;
        int d = dstA[e] - g * NN;
        atomicAdd(&S->a.cnt[d * NN + s], 1);
    }
    __syncthreads();

    if (tid < NN) {
        int deg = 1;
        for (int s = 0; s < NN; s++) deg += S->a.cnt[tid * NN + s];
        S->dis[tid] = rsqrtf((float)deg);
    }
    __syncthreads();

    for (int i = tid; i < NN * NN; i += 256) {
        int d = i / NN, s = i - d * NN;
        float c = (float)S->a.cnt[i];
        float v = c * S->dis[d] * S->dis[s];
        if (d == s) v += S->dis[d] * S->dis[d];
        S->a.Af[i] = v;
    }
    __syncthreads();

    int ch = tid & 127, half = tid >> 7;
    float pacc = 0.f;
    for (int nd = half; nd < NN; nd += 2) {
        const float* arow = &S->a.Af[nd * NN];
        float v0 = 0.f, v1 = 0.f;
        #pragma unroll 2
        for (int s = 0; s < NN; s += 2) {
            v0 = fmaf(arow[s],     S->xw[s * GH + ch],       v0);
            v1 = fmaf(arow[s + 1], S->xw[(s + 1) * GH + ch], v1);
        }
        pacc += fmaxf(v0 + v1 + S->bsm[ch], 0.f);
    }
    S->pool[half * GH + ch] = pacc;
    __syncthreads();

    if (tid < GH)
        S->gsm[tid] = (S->pool[tid] + S->pool[GH + tid]) * (1.0f / (float)NN);
    __syncthreads();

    if (tid < GH / 2) {
        float accv = b1[tid];
        #pragma unroll
        for (int c = 0; c < GH; c++)
            accv = fmaf(S->gsm[c], w1[c * (GH / 2) + tid], accv);
        S->zsm[tid] = fmaxf(accv, 0.f);
    }
    __syncthreads();

    if (tid < OUTD) {
        float accv = b2[tid];
        for (int j = 0; j < GH / 2; j++)
            accv = fmaf(S->zsm[j], w2[j * OUTD + tid], accv);
        out[g * OUTD + tid] = accv;
    }
}

extern "C" void kernel_launch(void* const* d_in, const int* in_sizes, int n_in,
                              void* d_out, int out_size)
{
    const float* x        = (const float*)d_in[0];
    const int*   edge_idx = (const int*)  d_in[1];
    const float* conv_w   = (const float*)d_in[3];
    const float* conv_b   = (const float*)d_in[4];
    const float* lin1_w   = (const float*)d_in[5];
    const float* lin1_b   = (const float*)d_in[6];
    const float* gcn_w    = (const float*)d_in[7];
    const float* gcn_b    = (const float*)d_in[8];
    const float* mlp_w1   = (const float*)d_in[9];
    const float* mlp_b1   = (const float*)d_in[10];
    const float* mlp_w2   = (const float*)d_in[11];
    const float* mlp_b2   = (const float*)d_in[12];
    float* out = (float*)d_out;

    cudaFuncSetAttribute(lin1_mma_kernel,
                         cudaFuncAttributeMaxDynamicSharedMemorySize, L1_TOTAL);
    cudaFuncSetAttribute(gcn_head_kernel,
                         cudaFuncAttributeMaxDynamicSharedMemorySize,
                         (int)sizeof(HeadSmem));

    conv_pool_kernel<<<TT, 256>>>(x, conv_w, conv_b);
    lin1_mma_kernel<<<dim3(NN, KSPLIT), 256, L1_TOTAL>>>(lin1_w);
    gcn_xw_kernel<<<TT / 4, 512>>>(lin1_b, gcn_w);
    gcn_head_kernel<<<BB, 256, sizeof(HeadSmem)>>>(
        edge_idx, gcn_b, mlp_w1, mlp_b1, mlp_w2, mlp_b2, out);
}